// round 5
// baseline (speedup 1.0000x reference)
#include <cuda_runtime.h>
#include <cuda_bf16.h>
#include <cuda_fp16.h>
#include <math.h>
#include <stdint.h>

#define NN 100000
#define NE 1600000

// ---------------- scratch (device globals: no allocation allowed) -------------
__device__ __half g_uh[NN * 64];   // u = (H @ W) * dis, fp16 (pre-aggregation)
__device__ __half g_h16[NN * 64];  // layer-1 output after aggregate+bias+relu (fp16)
__device__ float g_dis[NN];        // D^{-1/2}
__device__ float g_u3[NN];         // layer-3 scalar pre-aggregation
__device__ int   g_cnt[NN];        // in-degree (without self loop)
__device__ int   g_cur[NN];        // fill cursors
__device__ int   g_off[NN + 1];    // CSR offsets
__device__ int   g_part[256];      // scan partials
__device__ int   g_partx[256];     // scan partials (exclusive)
__device__ int   g_csr[NE];        // src per dst-sorted slot
__device__ int   g_is64;           // edge_index element width flag

// ---------------- streams/events for graph-level overlap ----------------------
static cudaStream_t s_side = nullptr;
static cudaEvent_t  s_evFork = nullptr, s_evJoin = nullptr;
namespace {
struct StreamInit {
    StreamInit() {
        cudaStreamCreateWithFlags(&s_side, cudaStreamNonBlocking);
        cudaEventCreateWithFlags(&s_evFork, cudaEventDisableTiming);
        cudaEventCreateWithFlags(&s_evJoin, cudaEventDisableTiming);
    }
} s_streamInit;
}

// ---------------- helpers ------------------------------------------------------
__device__ __forceinline__ uint32_t smem_u32(const void* p) {
    uint32_t a;
    asm("{ .reg .u64 t; cvta.to.shared.u64 t, %1; cvt.u32.u64 %0, t; }" : "=r"(a) : "l"(p));
    return a;
}
#define SWZ128(o) ((o) ^ (((o) >> 3) & 0x70))

__device__ __forceinline__ void ldsm_x4(uint32_t a, uint32_t& r0, uint32_t& r1,
                                        uint32_t& r2, uint32_t& r3) {
    asm volatile("ldmatrix.sync.aligned.m8n8.x4.shared.b16 {%0,%1,%2,%3}, [%4];"
                 : "=r"(r0), "=r"(r1), "=r"(r2), "=r"(r3) : "r"(a));
}
__device__ __forceinline__ void mma_bf16(float* d, const uint32_t* a, uint32_t b0, uint32_t b1) {
    asm volatile("mma.sync.aligned.m16n8k16.row.col.f32.bf16.bf16.f32 "
                 "{%0,%1,%2,%3}, {%4,%5,%6,%7}, {%8,%9}, {%0,%1,%2,%3};"
                 : "+f"(d[0]), "+f"(d[1]), "+f"(d[2]), "+f"(d[3])
                 : "r"(a[0]), "r"(a[1]), "r"(a[2]), "r"(a[3]), "r"(b0), "r"(b1));
}

// ---------------- edge dtype detection ---------------------------------------
__global__ void detect_dtype(const int* ei32) {
    int bad = (ei32[2 * threadIdx.x + 1] != 0) ? 1 : 0;
    int any = __syncthreads_or(bad);
    if (threadIdx.x == 0) g_is64 = any ? 0 : 1;
}

__device__ __forceinline__ void load_edge(const void* ei, int e, int is64, int& s, int& d) {
    if (is64) {
        const long long* p = (const long long*)ei;
        s = (int)p[e];
        d = (int)p[NE + e];
    } else {
        const int* p = (const int*)ei;
        s = p[e];
        d = p[NE + e];
    }
}

// ---------------- CSR build ---------------------------------------------------
__global__ void zero_k() {
    int i = blockIdx.x * blockDim.x + threadIdx.x;
    if (i < NN) { g_cnt[i] = 0; g_cur[i] = 0; }
}

__global__ void count_k(const void* ei) {
    int e = blockIdx.x * blockDim.x + threadIdx.x;
    if (e < NE) {
        int s, d;
        load_edge(ei, e, g_is64, s, d);
        atomicAdd(&g_cnt[d], 1);
    }
}

// dis only needs counts — lets GEMM1 start before the scan/fill chain
__global__ void dis_k() {
    int i = blockIdx.x * blockDim.x + threadIdx.x;
    if (i < NN) g_dis[i] = rsqrtf((float)g_cnt[i] + 1.0f);
}

// warp-shuffle inclusive scan, 512/block
__global__ void scan1() {
    __shared__ int sw[16];
    int t = threadIdx.x, lane = t & 31, w = t >> 5;
    int i = blockIdx.x * 512 + t;
    int v = (i < NN) ? g_cnt[i] : 0;
    int x = v;
    #pragma unroll
    for (int o = 1; o < 32; o <<= 1) {
        int y = __shfl_up_sync(0xffffffffu, x, o);
        if (lane >= o) x += y;
    }
    if (lane == 31) sw[w] = x;
    __syncthreads();
    if (w == 0) {
        int s = (lane < 16) ? sw[lane] : 0;
        #pragma unroll
        for (int o = 1; o < 16; o <<= 1) {
            int y = __shfl_up_sync(0xffffffffu, s, o);
            if (lane >= o) s += y;
        }
        if (lane < 16) sw[lane] = s;
    }
    __syncthreads();
    if (w) x += sw[w - 1];
    if (i < NN) g_off[i + 1] = x;
    if (t == 511) g_part[blockIdx.x] = x;
}

#define SCAN_NBLK 196  // ceil(100000/512)

__global__ void scan2() {
    __shared__ int sd[256];
    int t = threadIdx.x;
    int v = (t < SCAN_NBLK) ? g_part[t] : 0;
    sd[t] = v;
    __syncthreads();
    #pragma unroll
    for (int d = 1; d < 256; d <<= 1) {
        int x = (t >= d) ? sd[t - d] : 0;
        __syncthreads();
        sd[t] += x;
        __syncthreads();
    }
    if (t < SCAN_NBLK) g_partx[t] = sd[t] - v;  // exclusive
}

__global__ void scan3() {
    int i = blockIdx.x * blockDim.x + threadIdx.x;
    if (i < NN) {
        g_off[i + 1] += g_partx[i >> 9];
        if (i == 0) g_off[0] = 0;
    }
}

__global__ void fill_k(const void* ei) {
    int e = blockIdx.x * blockDim.x + threadIdx.x;
    if (e < NE) {
        int s, d;
        load_edge(ei, e, g_is64, s, d);
        int pos = g_off[d] + atomicAdd(&g_cur[d], 1);
        g_csr[pos] = s;
    }
}

// ---------------- MMA split-bf16 GEMM ------------------------------------------
// g_uh[row, 0:64] = fp16( (A[row, 0:K] @ W[K, 64]) * dis[row] )
// 256 rows/CTA, 8 warps x 32 rows. K staged in 64-chunks, SW128-swizzled smem.
// D = AhWh + AhWl + AlWh (fp32 acc). FROM_H: A is fp16 g_h16 (exact hi/lo split).
template <int KCHUNKS, bool FROM_H>
__global__ void __launch_bounds__(256)
gemm_mma(const float* __restrict__ Ain, const float* __restrict__ W) {
    extern __shared__ char dsm[];
    uint32_t sb0 = smem_u32(dsm);
    uint32_t sb = (sb0 + 1023) & ~1023u;
    char* p = dsm + (sb - sb0);
    const uint32_t AH = sb, AL = sb + 32768, BH = sb + 65536, BL = sb + 73728;
    char* pAH = p;
    char* pAL = p + 32768;
    char* pBH = p + 65536;
    char* pBL = p + 73728;

    constexpr int K = KCHUNKS * 64;
    const int tid = threadIdx.x, wid = tid >> 5, lane = tid & 31;
    const int row0 = blockIdx.x * 256;
    const int g = lane >> 2, tig = lane & 3;

    float acc[2][8][4];
    #pragma unroll
    for (int i = 0; i < 2; i++)
        #pragma unroll
        for (int j = 0; j < 8; j++)
            #pragma unroll
            for (int r = 0; r < 4; r++) acc[i][j][r] = 0.f;

    for (int ch = 0; ch < KCHUNKS; ch++) {
        __syncthreads();

        if (!FROM_H) {
            // fp32 source
            #pragma unroll
            for (int it = tid; it < 4096; it += 256) {   // 256 rows * 16 float4
                int r = it >> 4, c4 = it & 15;
                int row = row0 + r;
                float4 v = make_float4(0.f, 0.f, 0.f, 0.f);
                if (row < NN) v = ((const float4*)Ain)[(size_t)row * (K / 4) + ch * 16 + c4];
                __nv_bfloat16 hx = __float2bfloat16_rn(v.x);
                __nv_bfloat16 hy = __float2bfloat16_rn(v.y);
                __nv_bfloat16 hz = __float2bfloat16_rn(v.z);
                __nv_bfloat16 hw = __float2bfloat16_rn(v.w);
                __nv_bfloat16 lx = __float2bfloat16_rn(v.x - __bfloat162float(hx));
                __nv_bfloat16 ly = __float2bfloat16_rn(v.y - __bfloat162float(hy));
                __nv_bfloat16 lz = __float2bfloat16_rn(v.z - __bfloat162float(hz));
                __nv_bfloat16 lw = __float2bfloat16_rn(v.w - __bfloat162float(hw));
                uint32_t so = SWZ128((uint32_t)(r * 128 + c4 * 8));
                __nv_bfloat162 h01(hx, hy), h23(hz, hw), l01(lx, ly), l23(lz, lw);
                uint2 hv = make_uint2(*(uint32_t*)&h01, *(uint32_t*)&h23);
                uint2 lv = make_uint2(*(uint32_t*)&l01, *(uint32_t*)&l23);
                *(uint2*)(pAH + so) = hv;
                *(uint2*)(pAL + so) = lv;
            }
        } else {
            // fp16 source (g_h16), K=64: 256 rows x 8 uint4 (8 halves each)
            #pragma unroll
            for (int it = tid; it < 2048; it += 256) {
                int r = it >> 3, c8 = it & 7;
                int row = row0 + r;
                uint4 v = make_uint4(0, 0, 0, 0);
                if (row < NN) v = ((const uint4*)g_h16)[(size_t)row * 8 + c8];
                uint32_t hv[4], lv[4];
                const uint32_t* vv = &v.x;
                #pragma unroll
                for (int q = 0; q < 4; q++) {
                    float2 f = __half22float2(*(__half2*)&vv[q]);
                    __nv_bfloat16 h0 = __float2bfloat16_rn(f.x);
                    __nv_bfloat16 h1 = __float2bfloat16_rn(f.y);
                    __nv_bfloat16 l0 = __float2bfloat16_rn(f.x - __bfloat162float(h0));
                    __nv_bfloat16 l1 = __float2bfloat16_rn(f.y - __bfloat162float(h1));
                    __nv_bfloat162 hh(h0, h1), ll(l0, l1);
                    hv[q] = *(uint32_t*)&hh;
                    lv[q] = *(uint32_t*)&ll;
                }
                uint32_t so = SWZ128((uint32_t)(r * 128 + c8 * 16));
                *(uint4*)(pAH + so) = make_uint4(hv[0], hv[1], hv[2], hv[3]);
                *(uint4*)(pAL + so) = make_uint4(lv[0], lv[1], lv[2], lv[3]);
            }
        }
        #pragma unroll
        for (int it = tid; it < 4096; it += 256) {   // 64 k * 64 n
            int kloc = it >> 6, n = it & 63;
            float w = W[(size_t)(ch * 64 + kloc) * 64 + n];
            __nv_bfloat16 hw_ = __float2bfloat16_rn(w);
            __nv_bfloat16 lw_ = __float2bfloat16_rn(w - __bfloat162float(hw_));
            uint32_t so = SWZ128((uint32_t)(n * 128 + kloc * 2));
            *(__nv_bfloat16*)(pBH + so) = hw_;
            *(__nv_bfloat16*)(pBL + so) = lw_;
        }
        __syncthreads();

        #pragma unroll
        for (int ks = 0; ks < 4; ks++) {
            uint32_t ar   = (uint32_t)(wid * 32 + (lane & 15));
            uint32_t akb  = (uint32_t)(ks * 32 + ((lane >> 4) << 4));
            uint32_t aof0 = SWZ128(ar * 128 + akb);
            uint32_t aof1 = SWZ128((ar + 16) * 128 + akb);
            uint32_t ah0[4], ah1[4], al0[4], al1[4];
            ldsm_x4(AH + aof0, ah0[0], ah0[1], ah0[2], ah0[3]);
            ldsm_x4(AH + aof1, ah1[0], ah1[1], ah1[2], ah1[3]);
            ldsm_x4(AL + aof0, al0[0], al0[1], al0[2], al0[3]);
            ldsm_x4(AL + aof1, al1[0], al1[1], al1[2], al1[3]);

            uint32_t bkb = (uint32_t)(ks * 32 + (((lane >> 3) & 1) << 4));
            #pragma unroll
            for (int jj = 0; jj < 4; jj++) {
                uint32_t bn = (uint32_t)(jj * 16 + (lane & 7) + ((lane >> 4) << 3));
                uint32_t bof = SWZ128(bn * 128 + bkb);
                uint32_t bh[4], bl[4];
                ldsm_x4(BH + bof, bh[0], bh[1], bh[2], bh[3]);
                ldsm_x4(BL + bof, bl[0], bl[1], bl[2], bl[3]);
                mma_bf16(acc[0][2 * jj], ah0, bh[0], bh[1]);
                mma_bf16(acc[0][2 * jj], ah0, bl[0], bl[1]);
                mma_bf16(acc[0][2 * jj], al0, bh[0], bh[1]);
                mma_bf16(acc[1][2 * jj], ah1, bh[0], bh[1]);
                mma_bf16(acc[1][2 * jj], ah1, bl[0], bl[1]);
                mma_bf16(acc[1][2 * jj], al1, bh[0], bh[1]);
                mma_bf16(acc[0][2 * jj + 1], ah0, bh[2], bh[3]);
                mma_bf16(acc[0][2 * jj + 1], ah0, bl[2], bl[3]);
                mma_bf16(acc[0][2 * jj + 1], al0, bh[2], bh[3]);
                mma_bf16(acc[1][2 * jj + 1], ah1, bh[2], bh[3]);
                mma_bf16(acc[1][2 * jj + 1], ah1, bl[2], bl[3]);
                mma_bf16(acc[1][2 * jj + 1], al1, bh[2], bh[3]);
            }
        }
    }

    // ---- epilogue: scale by dis, store fp16 ----
    #pragma unroll
    for (int G = 0; G < 2; G++) {
        int r_lo = row0 + wid * 32 + G * 16 + g;
        int r_hi = r_lo + 8;
        float s_lo = (r_lo < NN) ? g_dis[r_lo] : 0.f;
        float s_hi = (r_hi < NN) ? g_dis[r_hi] : 0.f;
        #pragma unroll
        for (int j = 0; j < 8; j++) {
            int col = j * 8 + tig * 2;
            if (r_lo < NN)
                *(__half2*)&g_uh[(size_t)r_lo * 64 + col] =
                    __floats2half2_rn(acc[G][j][0] * s_lo, acc[G][j][1] * s_lo);
            if (r_hi < NN)
                *(__half2*)&g_uh[(size_t)r_hi * 64 + col] =
                    __floats2half2_rn(acc[G][j][2] * s_hi, acc[G][j][3] * s_hi);
        }
    }
}

// ---------------- aggregate + bias + relu (+ optional fused W3 dot) -----------
// One warp per node; lane owns 2 cols (half2). One coalesced 128B line per edge.
// h[d] = relu( dis[d] * ( sum_{e->d} u[src] + u[d] ) + b )
// FUSE_DOT: instead of writing h, compute u3[d] = dot(h[d], W3) * dis[d].
template <bool FUSE_DOT>
__global__ void agg_relu(const float* __restrict__ b, const float* __restrict__ W3) {
    int wid = threadIdx.x >> 5, lane = threadIdx.x & 31;
    int d = blockIdx.x * 8 + wid;  // 12500 blocks * 8 warps = 100000 exact

    const uint32_t* U = (const uint32_t*)g_uh;  // 32 half2-words per row
    float2 acc = __half22float2(*(__half2*)&U[(size_t)d * 32 + lane]);  // self term
    int e = g_off[d], end = g_off[d + 1];
    #pragma unroll 4
    for (; e < end; e++) {
        int s = g_csr[e];
        uint32_t r = U[(size_t)s * 32 + lane];
        float2 v = __half22float2(*(__half2*)&r);
        acc.x += v.x; acc.y += v.y;
    }
    float sc = g_dis[d];
    float2 bb = ((const float2*)b)[lane];
    float2 o;
    o.x = fmaxf(sc * acc.x + bb.x, 0.f);
    o.y = fmaxf(sc * acc.y + bb.y, 0.f);
    if (!FUSE_DOT) {
        *(__half2*)&g_h16[(size_t)d * 64 + lane * 2] = __floats2half2_rn(o.x, o.y);
    } else {
        float2 w3 = ((const float2*)W3)[lane];
        float dot = o.x * w3.x + o.y * w3.y;
        #pragma unroll
        for (int off = 16; off; off >>= 1) dot += __shfl_xor_sync(0xffffffffu, dot, off);
        if (lane == 0) g_u3[d] = dot * sc;
    }
}

// ---------------- final: out = sigmoid(dis*(sum u3 + u3[d]) + b3) -------------
__global__ void final_k(const float* __restrict__ b3, float* __restrict__ out) {
    int d = blockIdx.x * blockDim.x + threadIdx.x;
    if (d < NN) {
        float s = g_u3[d];
        int e = g_off[d], end = g_off[d + 1];
        #pragma unroll 4
        for (; e < end; e++) s += g_u3[g_csr[e]];
        float z = g_dis[d] * s + b3[0];
        out[d] = 1.0f / (1.0f + expf(-z));
    }
}

// ---------------- launch -------------------------------------------------------
extern "C" void kernel_launch(void* const* d_in, const int* in_sizes, int n_in,
                              void* d_out, int out_size) {
    const float* x  = (const float*)d_in[0];
    const float* W1 = (const float*)d_in[1];
    const float* b1 = (const float*)d_in[2];
    const float* W2 = (const float*)d_in[3];
    const float* b2 = (const float*)d_in[4];
    const float* W3 = (const float*)d_in[5];
    const float* b3 = (const float*)d_in[6];
    const void*  ei = d_in[7];
    float* out = (float*)d_out;

    const int SMEM = 1024 + 65536 + 16384;  // pad + A(hi/lo) + B(hi/lo) = 82944
    cudaFuncSetAttribute(gemm_mma<2, false>, cudaFuncAttributeMaxDynamicSharedMemorySize, SMEM);
    cudaFuncSetAttribute(gemm_mma<1, true>,  cudaFuncAttributeMaxDynamicSharedMemorySize, SMEM);

    const int NBLK = (NN + 255) / 256;  // 391

    // --- base stream: structure prefix ---
    detect_dtype<<<1, 256>>>((const int*)ei);
    zero_k<<<(NN + 255) / 256, 256>>>();
    count_k<<<(NE + 255) / 256, 256>>>(ei);
    dis_k<<<(NN + 255) / 256, 256>>>();

    // fork: gemm1 (needs only x, W1, dis) runs concurrently with scan+fill
    cudaEventRecord(s_evFork, 0);
    cudaStreamWaitEvent(s_side, s_evFork, 0);
    gemm_mma<2, false><<<NBLK, 256, SMEM, s_side>>>(x, W1);
    cudaEventRecord(s_evJoin, s_side);

    // base stream: scan + fill chain
    scan1<<<SCAN_NBLK, 512>>>();
    scan2<<<1, 256>>>();
    scan3<<<(NN + 255) / 256, 256>>>();
    fill_k<<<(NE + 255) / 256, 256>>>(ei);

    // join: agg1 needs both gemm1 and fill
    cudaStreamWaitEvent(0, s_evJoin, 0);

    // layer 1 aggregate
    agg_relu<false><<<NN / 8, 256>>>(b1, nullptr);
    // layer 2 (+ fused layer-3 dot)
    gemm_mma<1, true><<<NBLK, 256, SMEM>>>(nullptr, W2);
    agg_relu<true><<<NN / 8, 256>>>(b2, W3);
    // final
    final_k<<<(NN + 255) / 256, 256>>>(b3, out);
}